// round 1
// baseline (speedup 1.0000x reference)
#include <cuda_runtime.h>
#include <cuda_bf16.h>
#include <math.h>

// Problem constants
#define BB 32
#define SS 1024
#define DIN 128
#define HH 256
#define G4H 1024          // 4*H
#define HCAT 512          // 2*H

// ---------------- scratch (device globals; no cudaMalloc allowed) ----------
__device__ float g_xp[2u * SS * BB * G4H];        // [dir][s][b][4H]  268MB
__device__ float g_hcat0[(size_t)BB * SS * HCAT]; // [b][s][512]
__device__ float g_hcat1[(size_t)BB * SS * HCAT];
__device__ float g_ctx[(size_t)BB * SS * HCAT];
__device__ float g_h[2 * 2 * HH * BB];            // [dir][parity][k][b]
__device__ float g_s[BB * SS];
__device__ float g_mx[BB];
__device__ unsigned g_bar[2];

// ---------------------------------------------------------------------------
__device__ __forceinline__ float sigf(float x) { return 1.0f / (1.0f + expf(-x)); }

__device__ __forceinline__ unsigned ld_acq(const unsigned* p) {
    unsigned v;
    asm volatile("ld.acquire.gpu.u32 %0, [%1];" : "=r"(v) : "l"(p));
    return v;
}

__global__ void reset_bar_kernel() {
    if (threadIdx.x < 2) g_bar[threadIdx.x] = 0u;
}

// ---------------------------------------------------------------------------
// Tiled FP32 GEMM: out[m,n] = sum_k A[m,k] * W[n,k] + bias[n]
// BM=128, BN=64, BK=16, 256 threads, 8x4 per-thread tile.
// SRC: 0 = A param (x), 1 = g_hcat0, 2 = g_ctx
// EPI: 0 = proj (writes g_xp, dual dir weights), 1 = head (writes out param)
// ---------------------------------------------------------------------------
template <int SRC, int EPI>
__global__ __launch_bounds__(256) void gemm_kernel(
    const float* __restrict__ A_in, int K,
    const float* __restrict__ Wf, const float* __restrict__ Wb,
    const float* __restrict__ bf, const float* __restrict__ bb,
    float* __restrict__ out_p)
{
    __shared__ float As[16][132];
    __shared__ float Bs[16][68];

    const float* A = (SRC == 0) ? A_in : (SRC == 1 ? g_hcat0 : g_ctx);

    const int t  = threadIdx.x;
    const int tx = t & 15;
    const int ty = t >> 4;
    const int m0 = blockIdx.x * 128;
    const int n0 = blockIdx.y * 64;

    const float* Wp;
    const float* biasp;
    int wrow0;
    if (EPI == 0) {
        if (n0 < 1024) { Wp = Wf; biasp = bf; wrow0 = n0; }
        else           { Wp = Wb; biasp = bb; wrow0 = n0 - 1024; }
    } else {
        Wp = Wf; biasp = bf; wrow0 = n0;
    }

    float acc[8][4];
#pragma unroll
    for (int i = 0; i < 8; i++)
#pragma unroll
        for (int j = 0; j < 4; j++) acc[i][j] = 0.0f;

    const int nkt = K >> 4;
    for (int kt = 0; kt < nkt; kt++) {
        const int k0 = kt << 4;
        // stage A: 128 rows x 16 k = 512 float4 slots
#pragma unroll
        for (int r = 0; r < 2; r++) {
            int idx = t + r * 256;          // 0..511
            int row = idx >> 2;
            int kq  = idx & 3;
            float4 v = *(const float4*)&A[(size_t)(m0 + row) * K + k0 + kq * 4];
            As[kq * 4 + 0][row] = v.x;
            As[kq * 4 + 1][row] = v.y;
            As[kq * 4 + 2][row] = v.z;
            As[kq * 4 + 3][row] = v.w;
        }
        // stage B: 64 rows x 16 k = 256 float4 slots
        {
            int row = t >> 2;
            int kq  = t & 3;
            float4 v = *(const float4*)&Wp[(size_t)(wrow0 + row) * K + k0 + kq * 4];
            Bs[kq * 4 + 0][row] = v.x;
            Bs[kq * 4 + 1][row] = v.y;
            Bs[kq * 4 + 2][row] = v.z;
            Bs[kq * 4 + 3][row] = v.w;
        }
        __syncthreads();
#pragma unroll
        for (int kk = 0; kk < 16; kk++) {
            float af[8], bfr[4];
            *(float4*)&af[0]  = *(const float4*)&As[kk][ty * 8];
            *(float4*)&af[4]  = *(const float4*)&As[kk][ty * 8 + 4];
            *(float4*)&bfr[0] = *(const float4*)&Bs[kk][tx * 4];
#pragma unroll
            for (int i = 0; i < 8; i++)
#pragma unroll
                for (int j = 0; j < 4; j++)
                    acc[i][j] = fmaf(af[i], bfr[j], acc[i][j]);
        }
        __syncthreads();
    }

    // epilogue
#pragma unroll
    for (int i = 0; i < 8; i++) {
        int m = m0 + ty * 8 + i;
        int b = m >> 10;
        int s = m & 1023;
#pragma unroll
        for (int j = 0; j < 4; j++) {
            int c = tx * 4 + j;
            float v = acc[i][j] + biasp[wrow0 + c];
            if (EPI == 0) {
                int ng  = n0 + c;
                int dir = ng >> 10;
                int g   = ng & 1023;
                g_xp[((size_t)(dir * SS + s) * BB + b) * G4H + g] = v;
            } else {
                out_p[(size_t)m * 128 + (n0 + c)] = v;
            }
        }
    }
}

// ---------------------------------------------------------------------------
// Persistent bidirectional LSTM layer. 128 CTAs (64/dir), 128 threads.
// CTA owns 4 hidden units (16 W_hh rows, SMEM-resident). Per-step global
// barrier. h double-buffered in g_h, layout [dir][parity][k][b].
// ---------------------------------------------------------------------------
#define LSTM_SMEM ((4096 + 8192 + 512) * 4)

__global__ __launch_bounds__(128, 1) void lstm_kernel(
    const float* __restrict__ whf, const float* __restrict__ whb, int layer)
{
    extern __shared__ float sm[];
    float* sm_w = sm;            // [16][256]
    float* sm_h = sm + 4096;     // [256][32]
    float* sm_g = sm + 4096 + 8192; // [16][32]

    const int t     = threadIdx.x;
    const int dir   = blockIdx.x >> 6;
    const int slice = blockIdx.x & 63;
    const float* W  = dir ? whb : whf;
    float* hout     = (layer == 0) ? g_hcat0 : g_hcat1;
    unsigned* bar   = &g_bar[layer];

    // load weight slice: rows r = G*4+u -> W[(G*256 + slice*4 + u)][k]
    for (int e = t; e < 4096; e += 128) {
        int r = e >> 8, k = e & 255;
        int grow = ((r >> 2) << 8) + (slice << 2) + (r & 3);
        sm_w[e] = W[(size_t)grow * HH + k];
    }

    // compute mapping: rows pair, batch pair
    const int rp = t >> 4;          // 0..7
    const int bp = t & 15;          // 0..15
    const int r0 = rp * 2, r1 = rp * 2 + 1;
    const int b0 = bp * 2;
    const int gr0 = ((r0 >> 2) << 8) + (slice << 2) + (r0 & 3);
    const int gr1 = ((r1 >> 2) << 8) + (slice << 2) + (r1 & 3);

    // activation mapping: one (u, b) per thread
    const int au = t >> 5;          // 0..3
    const int ab = t & 31;          // 0..31
    float cstate = 0.0f;

    // init h parity 0 to zero for our rows
    g_h[((dir * 2 + 0) * HH + (slice << 2) + au) * BB + ab] = 0.0f;

    // barrier phase 1 (init visible)
    unsigned phase = 1;
    __threadfence();
    __syncthreads();
    if (t == 0) {
        atomicAdd(bar, 1u);
        while (ld_acq(bar) < 128u * phase) {}
    }
    __syncthreads();

    const float* xpd = g_xp + (size_t)dir * SS * BB * G4H;

    for (int s = 0; s < SS; s++) {
        const int p    = s & 1;
        const int tcur = dir ? (SS - 1 - s) : s;

        // prefetch xp for the 4 (r,b) outputs of this thread
        const float* xpb = xpd + (size_t)tcur * BB * G4H;
        float x00 = xpb[(size_t)b0 * G4H + gr0];
        float x01 = xpb[(size_t)(b0 + 1) * G4H + gr0];
        float x10 = xpb[(size_t)b0 * G4H + gr1];
        float x11 = xpb[(size_t)(b0 + 1) * G4H + gr1];

        // stage h_prev [k][b]
        const float4* gsrc = (const float4*)(g_h + (dir * 2 + p) * HH * BB);
        float4* dsth = (float4*)sm_h;
        for (int e = t; e < 2048; e += 128) dsth[e] = gsrc[e];
        __syncthreads();

        // compute 2 rows x 2 batches
        float a00 = 0.f, a01 = 0.f, a10 = 0.f, a11 = 0.f;
        const float* pw0 = sm_w + r0 * 256;
        const float* pw1 = sm_w + r1 * 256;
        const float* ph  = sm_h + b0;
#pragma unroll 8
        for (int k = 0; k < 256; k++) {
            float2 h2 = *(const float2*)ph;
            ph += 32;
            float w0 = pw0[k];
            float w1 = pw1[k];
            a00 = fmaf(w0, h2.x, a00);
            a01 = fmaf(w0, h2.y, a01);
            a10 = fmaf(w1, h2.x, a10);
            a11 = fmaf(w1, h2.y, a11);
        }
        sm_g[r0 * 32 + b0]     = a00 + x00;
        sm_g[r0 * 32 + b0 + 1] = a01 + x01;
        sm_g[r1 * 32 + b0]     = a10 + x10;
        sm_g[r1 * 32 + b0 + 1] = a11 + x11;
        __syncthreads();

        // activation: gates i,f,g,o at rows G*4+u
        {
            float gi = sm_g[(0 * 4 + au) * 32 + ab];
            float gf = sm_g[(1 * 4 + au) * 32 + ab];
            float gg = sm_g[(2 * 4 + au) * 32 + ab];
            float go = sm_g[(3 * 4 + au) * 32 + ab];
            cstate = sigf(gf) * cstate + sigf(gi) * tanhf(gg);
            float hv = sigf(go) * tanhf(cstate);
            g_h[((dir * 2 + (p ^ 1)) * HH + (slice << 2) + au) * BB + ab] = hv;
            hout[((size_t)ab * SS + tcur) * HCAT + dir * HH + (slice << 2) + au] = hv;
        }

        // global barrier
        phase++;
        __threadfence();
        __syncthreads();
        if (t == 0) {
            atomicAdd(bar, 1u);
            while (ld_acq(bar) < 128u * phase) {}
        }
        __syncthreads();
    }
}

// ---------------------------------------------------------------------------
// attention score: s[b,t] = dot(h[b,t,:], attn_w) + attn_b ; per-b max
// ---------------------------------------------------------------------------
__global__ __launch_bounds__(256) void score_kernel(
    const float* __restrict__ attn_w, const float* __restrict__ attn_b)
{
    __shared__ float aw[HCAT];
    __shared__ float red[8];
    const int b = blockIdx.x;
    const int t = threadIdx.x;
    const int w = t >> 5, l = t & 31;
    for (int j = t; j < HCAT; j += 256) aw[j] = attn_w[j];
    __syncthreads();

    const float ab = attn_b[0];
    float mloc = -1e30f;
    for (int tt = w; tt < SS; tt += 8) {
        const float* hp = g_hcat1 + ((size_t)b * SS + tt) * HCAT;
        float sum = 0.f;
        for (int j = l; j < HCAT; j += 32) sum = fmaf(hp[j], aw[j], sum);
#pragma unroll
        for (int o = 16; o > 0; o >>= 1) sum += __shfl_xor_sync(0xFFFFFFFFu, sum, o);
        float sv = sum + ab;
        if (l == 0) g_s[b * SS + tt] = sv;
        mloc = fmaxf(mloc, sv);
    }
    if (l == 0) red[w] = mloc;
    __syncthreads();
    if (t == 0) {
        float m = red[0];
#pragma unroll
        for (int i = 1; i < 8; i++) m = fmaxf(m, red[i]);
        g_mx[b] = m;
    }
}

// ---------------------------------------------------------------------------
// cumulative softmax context: ctx[b,t,:] = cumsum(e*h)/cumsum(e)
// ---------------------------------------------------------------------------
__global__ __launch_bounds__(512) void ctx_kernel()
{
    const int b = blockIdx.x;
    const int j = threadIdx.x;
    const float mx = g_mx[b];
    float num = 0.f, den = 0.f;
    const float* sb = g_s + b * SS;
    for (int t = 0; t < SS; t++) {
        float e = expf(sb[t] - mx);
        den += e;
        size_t off = ((size_t)b * SS + t) * HCAT + j;
        num = fmaf(e, g_hcat1[off], num);
        g_ctx[off] = num / den;
    }
}

// ---------------------------------------------------------------------------
extern "C" void kernel_launch(void* const* d_in, const int* in_sizes, int n_in,
                              void* d_out, int out_size)
{
    const float* x        = (const float*)d_in[0];
    const float* w_ih_l0f = (const float*)d_in[1];
    const float* w_hh_l0f = (const float*)d_in[2];
    const float* b_l0f    = (const float*)d_in[3];
    const float* w_ih_l0b = (const float*)d_in[4];
    const float* w_hh_l0b = (const float*)d_in[5];
    const float* b_l0b    = (const float*)d_in[6];
    const float* w_ih_l1f = (const float*)d_in[7];
    const float* w_hh_l1f = (const float*)d_in[8];
    const float* b_l1f    = (const float*)d_in[9];
    const float* w_ih_l1b = (const float*)d_in[10];
    const float* w_hh_l1b = (const float*)d_in[11];
    const float* b_l1b    = (const float*)d_in[12];
    const float* attn_w   = (const float*)d_in[13];
    const float* attn_b   = (const float*)d_in[14];
    const float* head_w   = (const float*)d_in[15];
    const float* head_b   = (const float*)d_in[16];
    float* out = (float*)d_out;

    cudaFuncSetAttribute(lstm_kernel, cudaFuncAttributeMaxDynamicSharedMemorySize, LSTM_SMEM);

    reset_bar_kernel<<<1, 32>>>();

    // layer 0: projection + recurrence
    gemm_kernel<0, 0><<<dim3(256, 32), 256>>>(x, DIN, w_ih_l0f, w_ih_l0b, b_l0f, b_l0b, nullptr);
    lstm_kernel<<<128, 128, LSTM_SMEM>>>(w_hh_l0f, w_hh_l0b, 0);

    // layer 1: projection (A = g_hcat0) + recurrence
    gemm_kernel<1, 0><<<dim3(256, 32), 256>>>(nullptr, HCAT, w_ih_l1f, w_ih_l1b, b_l1f, b_l1b, nullptr);
    lstm_kernel<<<128, 128, LSTM_SMEM>>>(w_hh_l1f, w_hh_l1b, 1);

    // attention + context + head
    score_kernel<<<32, 256>>>(attn_w, attn_b);
    ctx_kernel<<<32, 512>>>();
    gemm_kernel<2, 1><<<dim3(256, 2), 256>>>(nullptr, HCAT, head_w, nullptr, head_b, nullptr, out);
}